// round 1
// baseline (speedup 1.0000x reference)
#include <cuda_runtime.h>

// 2-layer GRU (PyTorch semantics) + linear head.
// T=512, B=4096, I=2, H=64. Persistent batch-sliced blocks:
// each block owns BT=32 batch rows for the entire sequence, both layers.
// Weights live in SMEM; h states live in SMEM as duplicated float2 (for f32x2 FMA).

#define TT   512
#define BB   4096
#define II   2
#define HH   64
#define GG   192      // 3*H
#define BT   32       // batch rows per block
#define NBLK (BB/BT)  // 128
#define NTHR 128

typedef unsigned long long u64;

__device__ __forceinline__ void unpack2(u64 v, float& lo, float& hi) {
    asm("mov.b64 {%0,%1}, %2;" : "=f"(lo), "=f"(hi) : "l"(v));
}
__device__ __forceinline__ void ffma2(u64& d, u64 a, u64 b) {
    asm("fma.rn.f32x2 %0, %1, %2, %0;" : "+l"(d) : "l"(a), "l"(b));
}
__device__ __forceinline__ float sigm(float x) {
    return 1.0f / (1.0f + __expf(-x));
}
__device__ __forceinline__ float tanh_(float x) {
    return 1.0f - __fdividef(2.0f, __expf(2.0f * x) + 1.0f);
}

// SMEM layout (floats):
//   w0T  [64][192]   : Whh0^T           (w0T[k][g] = Whh0[g][k])
//   w1T  [128][192]  : [Wih1;Whh1]^T    (rows 0..63 = Wih1, 64..127 = Whh1)
//   hd   [128][32][2]: duplicated h; rows 0..63 = layer0 h, 64..127 = layer1 h
//   wx   [64][6]     : Wih0 rows for r,z,n (2 inputs each)
//   bc0  [64][4]     : layer0 biases: br(=bih+bhh), bz(=..), bnx(=bih_n), bnh(=bhh_n)
//   bc1  [64][4]     : layer1 biases likewise
#define OFF_W0T 0
#define OFF_W1T (OFF_W0T + 64*GG)
#define OFF_HD  (OFF_W1T + 128*GG)
#define OFF_WX  (OFF_HD  + 128*BT*2)
#define OFF_BC0 (OFF_WX  + 64*6)
#define OFF_BC1 (OFF_BC0 + 64*4)
#define SMEM_FLOATS (OFF_BC1 + 64*4)
#define SMEM_BYTES  (SMEM_FLOATS * 4)

extern "C" __global__ void __launch_bounds__(NTHR, 1)
gru2_kernel(const float* __restrict__ gx,
            const float* __restrict__ Wih0, const float* __restrict__ Whh0,
            const float* __restrict__ bih0, const float* __restrict__ bhh0,
            const float* __restrict__ Wih1, const float* __restrict__ Whh1,
            const float* __restrict__ bih1, const float* __restrict__ bhh1,
            const float* __restrict__ Wp,   const float* __restrict__ bp,
            float* __restrict__ out)
{
    extern __shared__ float sm[];
    float* w0T = sm + OFF_W0T;
    float* w1T = sm + OFF_W1T;
    float* hd  = sm + OFF_HD;
    float* wx  = sm + OFF_WX;
    float* bc0 = sm + OFF_BC0;
    float* bc1 = sm + OFF_BC1;

    const int tid = threadIdx.x;

    // ---- one-time weight staging ----
    for (int i = tid; i < GG * HH; i += NTHR) {
        int g = i / HH, k = i % HH;
        w0T[k * GG + g]        = Whh0[i];
        w1T[k * GG + g]        = Wih1[i];
        w1T[(64 + k) * GG + g] = Whh1[i];
    }
    for (int j = tid; j < HH; j += NTHR) {
        wx[j*6+0] = Wih0[j*2+0];         wx[j*6+1] = Wih0[j*2+1];
        wx[j*6+2] = Wih0[(64+j)*2+0];    wx[j*6+3] = Wih0[(64+j)*2+1];
        wx[j*6+4] = Wih0[(128+j)*2+0];   wx[j*6+5] = Wih0[(128+j)*2+1];
        bc0[j*4+0] = bih0[j]     + bhh0[j];
        bc0[j*4+1] = bih0[64+j]  + bhh0[64+j];
        bc0[j*4+2] = bih0[128+j];
        bc0[j*4+3] = bhh0[128+j];
        bc1[j*4+0] = bih1[j]     + bhh1[j];
        bc1[j*4+1] = bih1[64+j]  + bhh1[64+j];
        bc1[j*4+2] = bih1[128+j];
        bc1[j*4+3] = bhh1[128+j];
    }
    for (int i = tid; i < 128 * BT * 2; i += NTHR) hd[i] = 0.0f;
    __syncthreads();

    // thread tiling: jpg in [0,16) covers j0 = jpg*4 .. +3 ; bg in [0,8) covers b0 = bg*4 .. +3
    const int jpg = tid & 15;
    const int bg  = tid >> 4;
    const int j0  = jpg * 4;
    const int b0  = bg * 4;
    const int bglob = blockIdx.x * BT + b0;

    // x for current step in registers (prefetched one step ahead)
    float x0c[4], x1c[4];
    {
        const float* xp = gx;
        #pragma unroll
        for (int b = 0; b < 4; ++b) {
            float2 v = *(const float2*)(xp + (size_t)(bglob + b) * 2);
            x0c[b] = v.x; x1c[b] = v.y;
        }
    }

    for (int t = 0; t < TT; ++t) {
        // prefetch next x (global; cheap, latency hidden under the GEMM loops)
        float nx0[4], nx1[4];
        {
            int tn = (t + 1 < TT) ? t + 1 : t;
            const float* xp = gx + (size_t)tn * BB * II;
            #pragma unroll
            for (int b = 0; b < 4; ++b) {
                float2 v = *(const float2*)(xp + (size_t)(bglob + b) * 2);
                nx0[b] = v.x; nx1[b] = v.y;
            }
        }

        // ================= layer 0 recurrent GEMM: hg = h0 @ Whh0^T =================
        u64 aR[4][2], aZ[4][2], aN[4][2];
        #pragma unroll
        for (int b = 0; b < 4; ++b) {
            aR[b][0]=0ull; aR[b][1]=0ull;
            aZ[b][0]=0ull; aZ[b][1]=0ull;
            aN[b][0]=0ull; aN[b][1]=0ull;
        }
        #pragma unroll 2
        for (int k = 0; k < HH; ++k) {
            const float* wr = w0T + k * GG;
            ulonglong2 wR = *(const ulonglong2*)(wr + j0);
            ulonglong2 wZ = *(const ulonglong2*)(wr + 64 + j0);
            ulonglong2 wN = *(const ulonglong2*)(wr + 128 + j0);
            const float* hrow = hd + (k * BT + b0) * 2;
            ulonglong2 h01 = *(const ulonglong2*)(hrow);
            ulonglong2 h23 = *(const ulonglong2*)(hrow + 4);
            u64 hb[4] = { h01.x, h01.y, h23.x, h23.y };
            #pragma unroll
            for (int b = 0; b < 4; ++b) {
                ffma2(aR[b][0], hb[b], wR.x); ffma2(aR[b][1], hb[b], wR.y);
                ffma2(aZ[b][0], hb[b], wZ.x); ffma2(aZ[b][1], hb[b], wZ.y);
                ffma2(aN[b][0], hb[b], wN.x); ffma2(aN[b][1], hb[b], wN.y);
            }
        }

        // ---- layer 0 elementwise ----
        float hn0[4][4];
        #pragma unroll
        for (int p = 0; p < 2; ++p) {
            #pragma unroll
            for (int jj = 0; jj < 2; ++jj) {
                const int j = j0 + p * 2 + jj;
                const float wxr0 = wx[j*6+0], wxr1 = wx[j*6+1];
                const float wxz0 = wx[j*6+2], wxz1 = wx[j*6+3];
                const float wxn0 = wx[j*6+4], wxn1 = wx[j*6+5];
                const float br = bc0[j*4+0], bz = bc0[j*4+1];
                const float bnx = bc0[j*4+2], bnh = bc0[j*4+3];
                #pragma unroll
                for (int b = 0; b < 4; ++b) {
                    float lo, hi, aRv, aZv, aNv;
                    unpack2(aR[b][p], lo, hi); aRv = jj ? hi : lo;
                    unpack2(aZ[b][p], lo, hi); aZv = jj ? hi : lo;
                    unpack2(aN[b][p], lo, hi); aNv = jj ? hi : lo;
                    float r = sigm(aRv + x0c[b]*wxr0 + x1c[b]*wxr1 + br);
                    float z = sigm(aZv + x0c[b]*wxz0 + x1c[b]*wxz1 + bz);
                    float n = tanh_(x0c[b]*wxn0 + x1c[b]*wxn1 + bnx + r * (aNv + bnh));
                    float hold = hd[(j * BT + b0 + b) * 2];
                    hn0[b][p*2+jj] = n + z * (hold - n);
                }
            }
        }
        __syncthreads();   // all reads of old h0 complete
        #pragma unroll
        for (int jj = 0; jj < 4; ++jj) {
            const int j = j0 + jj;
            #pragma unroll
            for (int b = 0; b < 4; ++b) {
                float v = hn0[b][jj];
                *(float2*)(hd + (j * BT + b0 + b) * 2) = make_float2(v, v);
            }
        }
        __syncthreads();   // new h0 visible

        // ===== layer 1 fused GEMM: [h0_new, h1] @ [Wih1;Whh1]^T (n-gate split) =====
        u64 cR[4][2], cZ[4][2], cNx[4][2], cNh[4][2];
        #pragma unroll
        for (int b = 0; b < 4; ++b) {
            cR[b][0]=0ull; cR[b][1]=0ull;  cZ[b][0]=0ull;  cZ[b][1]=0ull;
            cNx[b][0]=0ull; cNx[b][1]=0ull; cNh[b][0]=0ull; cNh[b][1]=0ull;
        }
        #pragma unroll 2
        for (int k = 0; k < 64; ++k) {            // input-side (Wih1, reads new h0)
            const float* wr = w1T + k * GG;
            ulonglong2 wR = *(const ulonglong2*)(wr + j0);
            ulonglong2 wZ = *(const ulonglong2*)(wr + 64 + j0);
            ulonglong2 wN = *(const ulonglong2*)(wr + 128 + j0);
            const float* hrow = hd + (k * BT + b0) * 2;
            ulonglong2 h01 = *(const ulonglong2*)(hrow);
            ulonglong2 h23 = *(const ulonglong2*)(hrow + 4);
            u64 hb[4] = { h01.x, h01.y, h23.x, h23.y };
            #pragma unroll
            for (int b = 0; b < 4; ++b) {
                ffma2(cR[b][0],  hb[b], wR.x); ffma2(cR[b][1],  hb[b], wR.y);
                ffma2(cZ[b][0],  hb[b], wZ.x); ffma2(cZ[b][1],  hb[b], wZ.y);
                ffma2(cNx[b][0], hb[b], wN.x); ffma2(cNx[b][1], hb[b], wN.y);
            }
        }
        #pragma unroll 2
        for (int k = 64; k < 128; ++k) {          // recurrent side (Whh1, reads old h1)
            const float* wr = w1T + k * GG;
            ulonglong2 wR = *(const ulonglong2*)(wr + j0);
            ulonglong2 wZ = *(const ulonglong2*)(wr + 64 + j0);
            ulonglong2 wN = *(const ulonglong2*)(wr + 128 + j0);
            const float* hrow = hd + (k * BT + b0) * 2;
            ulonglong2 h01 = *(const ulonglong2*)(hrow);
            ulonglong2 h23 = *(const ulonglong2*)(hrow + 4);
            u64 hb[4] = { h01.x, h01.y, h23.x, h23.y };
            #pragma unroll
            for (int b = 0; b < 4; ++b) {
                ffma2(cR[b][0],  hb[b], wR.x); ffma2(cR[b][1],  hb[b], wR.y);
                ffma2(cZ[b][0],  hb[b], wZ.x); ffma2(cZ[b][1],  hb[b], wZ.y);
                ffma2(cNh[b][0], hb[b], wN.x); ffma2(cNh[b][1], hb[b], wN.y);
            }
        }

        // ---- layer 1 elementwise ----
        float hn1[4][4];
        #pragma unroll
        for (int p = 0; p < 2; ++p) {
            #pragma unroll
            for (int jj = 0; jj < 2; ++jj) {
                const int j = j0 + p * 2 + jj;
                const float br = bc1[j*4+0], bz = bc1[j*4+1];
                const float bnx = bc1[j*4+2], bnh = bc1[j*4+3];
                #pragma unroll
                for (int b = 0; b < 4; ++b) {
                    float lo, hi, cRv, cZv, cNxv, cNhv;
                    unpack2(cR[b][p],  lo, hi); cRv  = jj ? hi : lo;
                    unpack2(cZ[b][p],  lo, hi); cZv  = jj ? hi : lo;
                    unpack2(cNx[b][p], lo, hi); cNxv = jj ? hi : lo;
                    unpack2(cNh[b][p], lo, hi); cNhv = jj ? hi : lo;
                    float r = sigm(cRv + br);
                    float z = sigm(cZv + bz);
                    float n = tanh_(cNxv + bnx + r * (cNhv + bnh));
                    float hold = hd[((64 + j) * BT + b0 + b) * 2];
                    hn1[b][p*2+jj] = n + z * (hold - n);
                }
            }
        }
        __syncthreads();   // all reads of old h1 complete
        #pragma unroll
        for (int jj = 0; jj < 4; ++jj) {
            const int j = j0 + jj;
            #pragma unroll
            for (int b = 0; b < 4; ++b) {
                float v = hn1[b][jj];
                *(float2*)(hd + ((64 + j) * BT + b0 + b) * 2) = make_float2(v, v);
            }
        }
        __syncthreads();   // new h1 visible

        #pragma unroll
        for (int b = 0; b < 4; ++b) { x0c[b] = nx0[b]; x1c[b] = nx1[b]; }
    }

    // ---- projection: out[b] = [h0f, h1f] @ Wp^T + bp ----
    {
        const int b = tid >> 2;      // 0..31
        const int seg = tid & 3;     // 0..3 -> 32 features each
        float s = 0.0f;
        #pragma unroll
        for (int c = seg * 32; c < seg * 32 + 32; ++c)
            s += Wp[c] * hd[(c * BT + b) * 2];   // rows 0..63 = h0f, 64..127 = h1f
        s += __shfl_xor_sync(0xffffffffu, s, 1);
        s += __shfl_xor_sync(0xffffffffu, s, 2);
        if (seg == 0) out[blockIdx.x * BT + b] = s + bp[0];
    }
}

extern "C" void kernel_launch(void* const* d_in, const int* in_sizes, int n_in,
                              void* d_out, int out_size)
{
    (void)in_sizes; (void)n_in; (void)out_size;
    const float* x    = (const float*)d_in[0];
    const float* Wih0 = (const float*)d_in[1];
    const float* Whh0 = (const float*)d_in[2];
    const float* bih0 = (const float*)d_in[3];
    const float* bhh0 = (const float*)d_in[4];
    const float* Wih1 = (const float*)d_in[5];
    const float* Whh1 = (const float*)d_in[6];
    const float* bih1 = (const float*)d_in[7];
    const float* bhh1 = (const float*)d_in[8];
    const float* Wp   = (const float*)d_in[9];
    const float* bp   = (const float*)d_in[10];
    float* out = (float*)d_out;

    cudaFuncSetAttribute(gru2_kernel, cudaFuncAttributeMaxDynamicSharedMemorySize, SMEM_BYTES);
    gru2_kernel<<<NBLK, NTHR, SMEM_BYTES>>>(x, Wih0, Whh0, bih0, bhh0,
                                            Wih1, Whh1, bih1, bhh1, Wp, bp, out);
}

// round 2
// speedup vs baseline: 1.2104x; 1.2104x over previous
#include <cuda_runtime.h>

// 2-layer GRU (PyTorch semantics) + linear head. T=512, B=4096, I=2, H=64.
// 128 persistent blocks x 256 threads; each block owns BT=32 batch rows.
// k-split + layer pipeline: thread-half 0 (tid<128) and half 1 (tid>=128) each
// compute half of every GEMM; half 1's partials flow through SMEM scratch and
// half 0 reduces + does elementwise. Half 1 overlaps layer1-recurrent / next-step
// layer0 GEMMs with half 0's elementwise phases.
// All accumulation in packed fma.rn.f32x2 (2 FMA/lane/instr).

#define TT   512
#define BB   4096
#define II   2
#define HH   64
#define GG   192      // 3*H
#define BT   32       // batch rows per block
#define NBLK (BB/BT)  // 128
#define NTHR 256

typedef unsigned long long u64;

__device__ __forceinline__ void unpack2(u64 v, float& lo, float& hi) {
    asm("mov.b64 {%0,%1}, %2;" : "=f"(lo), "=f"(hi) : "l"(v));
}
__device__ __forceinline__ void ffma2(u64& d, u64 a, u64 b) {
    asm("fma.rn.f32x2 %0, %1, %2, %0;" : "+l"(d) : "l"(a), "l"(b));
}
__device__ __forceinline__ void fadd2(u64& d, u64 a) {
    asm("add.rn.f32x2 %0, %0, %1;" : "+l"(d) : "l"(a));
}
__device__ __forceinline__ float sigm(float x) {
    return 1.0f / (1.0f + __expf(-x));
}
__device__ __forceinline__ float tanh_(float x) {
    return 1.0f - __fdividef(2.0f, __expf(2.0f * x) + 1.0f);
}

#define BAR_ALL() asm volatile("bar.sync 0;" ::: "memory")
#define BAR_K0()  asm volatile("bar.sync 1, 128;" ::: "memory")

// SMEM layout (float index):
//   w0T  [64][192]    : Whh0^T            (w0T[k][g] = Whh0[g][k])
//   w1T  [128][192]   : [Wih1;Whh1]^T     (rows 0..63 = Wih1, 64..127 = Whh1)
//   hd   [128][32][2] : duplicated h; rows 0..63 = h0, 64..127 = h1
//   scrA [24][128] u64: layer0 partials from half 1
//   scrB [24][128] u64: layer1 partials from half 1
#define OFF_W0T  0
#define OFF_W1T  (OFF_W0T + 64*GG)          // 12288
#define OFF_HD   (OFF_W1T + 128*GG)         // 36864
#define OFF_SCRA (OFF_HD  + 128*BT*2)       // 45056
#define OFF_SCRB (OFF_SCRA + 24*128*2)      // 51200
#define SMEM_FLOATS (OFF_SCRB + 24*128*2)   // 57344
#define SMEM_BYTES  (SMEM_FLOATS * 4)       // 229376

template<int KBEG, int KEND>
__device__ __forceinline__ void gemm3(const float* __restrict__ wT,
                                      const float* __restrict__ hd,
                                      int j0, int b0,
                                      u64 aR[4][2], u64 aZ[4][2], u64 aN[4][2])
{
    #pragma unroll 4
    for (int k = KBEG; k < KEND; ++k) {
        const float* wr = wT + k * GG;
        ulonglong2 wR = *(const ulonglong2*)(wr + j0);
        ulonglong2 wZ = *(const ulonglong2*)(wr + 64 + j0);
        ulonglong2 wN = *(const ulonglong2*)(wr + 128 + j0);
        const float* hrow = hd + (k * BT + b0) * 2;
        ulonglong2 h01 = *(const ulonglong2*)(hrow);
        ulonglong2 h23 = *(const ulonglong2*)(hrow + 4);
        u64 hb[4] = { h01.x, h01.y, h23.x, h23.y };
        #pragma unroll
        for (int b = 0; b < 4; ++b) {
            ffma2(aR[b][0], hb[b], wR.x); ffma2(aR[b][1], hb[b], wR.y);
            ffma2(aZ[b][0], hb[b], wZ.x); ffma2(aZ[b][1], hb[b], wZ.y);
            ffma2(aN[b][0], hb[b], wN.x); ffma2(aN[b][1], hb[b], wN.y);
        }
    }
}

__device__ __forceinline__ void acc_zero(u64 a[4][2]) {
    #pragma unroll
    for (int b = 0; b < 4; ++b) { a[b][0] = 0ull; a[b][1] = 0ull; }
}

__device__ __forceinline__ void scr_write(u64* __restrict__ scr, int ht,
                                          u64 aR[4][2], u64 aZ[4][2], u64 aN[4][2])
{
    #pragma unroll
    for (int b = 0; b < 4; ++b) {
        #pragma unroll
        for (int p = 0; p < 2; ++p) {
            scr[(b*2+p)      * 128 + ht] = aR[b][p];
            scr[(8 + b*2+p)  * 128 + ht] = aZ[b][p];
            scr[(16 + b*2+p) * 128 + ht] = aN[b][p];
        }
    }
}

// add R,Z,N partials (layer 0 reduce)
__device__ __forceinline__ void scr_reduce(const u64* __restrict__ scr, int ht,
                                           u64 aR[4][2], u64 aZ[4][2], u64 aN[4][2])
{
    #pragma unroll
    for (int b = 0; b < 4; ++b) {
        #pragma unroll
        for (int p = 0; p < 2; ++p) {
            fadd2(aR[b][p], scr[(b*2+p)      * 128 + ht]);
            fadd2(aZ[b][p], scr[(8 + b*2+p)  * 128 + ht]);
            fadd2(aN[b][p], scr[(16 + b*2+p) * 128 + ht]);
        }
    }
}

// add R,Z; load Nh separately (layer 1 reduce: n-gate halves stay split)
__device__ __forceinline__ void scr_reduce_l1(const u64* __restrict__ scr, int ht,
                                              u64 cR[4][2], u64 cZ[4][2], u64 cNh[4][2])
{
    #pragma unroll
    for (int b = 0; b < 4; ++b) {
        #pragma unroll
        for (int p = 0; p < 2; ++p) {
            fadd2(cR[b][p], scr[(b*2+p)     * 128 + ht]);
            fadd2(cZ[b][p], scr[(8 + b*2+p) * 128 + ht]);
            cNh[b][p] = scr[(16 + b*2+p) * 128 + ht];
        }
    }
}

extern "C" __global__ void __launch_bounds__(NTHR, 1)
gru2_kernel(const float* __restrict__ gx,
            const float* __restrict__ Wih0, const float* __restrict__ Whh0,
            const float* __restrict__ bih0, const float* __restrict__ bhh0,
            const float* __restrict__ Wih1, const float* __restrict__ Whh1,
            const float* __restrict__ bih1, const float* __restrict__ bhh1,
            const float* __restrict__ Wp,   const float* __restrict__ bp,
            float* __restrict__ out)
{
    extern __shared__ float sm[];
    float* w0T = sm + OFF_W0T;
    float* w1T = sm + OFF_W1T;
    float* hd  = sm + OFF_HD;
    u64*   scrA = (u64*)(sm + OFF_SCRA);
    u64*   scrB = (u64*)(sm + OFF_SCRB);

    const int tid = threadIdx.x;
    const int kh  = tid >> 7;       // 0: reducer/elementwise half, 1: producer half
    const int ht  = tid & 127;
    const int jpg = ht & 15;
    const int bg  = ht >> 4;
    const int j0  = jpg * 4;
    const int b0  = bg * 4;
    const int bglob = blockIdx.x * BT + b0;

    // ---- one-time weight staging (all 256 threads) ----
    for (int i = tid; i < GG * HH; i += NTHR) {
        int g = i / HH, k = i % HH;
        w0T[k * GG + g]        = Whh0[i];
        w1T[k * GG + g]        = Wih1[i];
        w1T[(64 + k) * GG + g] = Whh1[i];
    }
    // zero hd + scratch
    for (int i = tid; i < SMEM_FLOATS - OFF_HD; i += NTHR) sm[OFF_HD + i] = 0.0f;

    // half-0 per-thread register weights / biases (rows j0..j0+3)
    float wxv[4][6], bc0v[4][4], bc1v[4][4];
    float x0c[4], x1c[4];
    if (kh == 0) {
        #pragma unroll
        for (int jj = 0; jj < 4; ++jj) {
            int j = j0 + jj;
            wxv[jj][0] = Wih0[j*2+0];        wxv[jj][1] = Wih0[j*2+1];
            wxv[jj][2] = Wih0[(64+j)*2+0];   wxv[jj][3] = Wih0[(64+j)*2+1];
            wxv[jj][4] = Wih0[(128+j)*2+0];  wxv[jj][5] = Wih0[(128+j)*2+1];
            bc0v[jj][0] = bih0[j]     + bhh0[j];
            bc0v[jj][1] = bih0[64+j]  + bhh0[64+j];
            bc0v[jj][2] = bih0[128+j];
            bc0v[jj][3] = bhh0[128+j];
            bc1v[jj][0] = bih1[j]     + bhh1[j];
            bc1v[jj][1] = bih1[64+j]  + bhh1[64+j];
            bc1v[jj][2] = bih1[128+j];
            bc1v[jj][3] = bhh1[128+j];
        }
        #pragma unroll
        for (int b = 0; b < 4; ++b) {
            float2 v = *(const float2*)(gx + (size_t)(bglob + b) * 2);
            x0c[b] = v.x; x1c[b] = v.y;
        }
    }
    BAR_ALL();

    for (int t = 0; t < TT; ++t) {
        if (kh == 0) {
            // ---- phase 1: layer0 GEMM, k 0..31 (reads hd0 = h0(t-1)) ----
            // prefetch x(t+1)
            float nx0[4], nx1[4];
            {
                int tn = (t + 1 < TT) ? t + 1 : t;
                const float* xp = gx + (size_t)tn * BB * II;
                #pragma unroll
                for (int b = 0; b < 4; ++b) {
                    float2 v = *(const float2*)(xp + (size_t)(bglob + b) * 2);
                    nx0[b] = v.x; nx1[b] = v.y;
                }
            }
            u64 aR[4][2], aZ[4][2], aN[4][2];
            acc_zero(aR); acc_zero(aZ); acc_zero(aN);
            gemm3<0, 32>(w0T, hd, j0, b0, aR, aZ, aN);
            BAR_K0();                      // half-0 internal: hd0 reads done

            // ---- phase 2: reduce + layer0 elementwise, write hd0 = h0(t) ----
            scr_reduce(scrA, ht, aR, aZ, aN);
            float hn0v[4][4];
            #pragma unroll
            for (int jj = 0; jj < 4; ++jj) {
                const int p = jj >> 1, hi = jj & 1;
                #pragma unroll
                for (int b = 0; b < 4; ++b) {
                    float l, h, aRv, aZv, aNv;
                    unpack2(aR[b][p], l, h); aRv = hi ? h : l;
                    unpack2(aZ[b][p], l, h); aZv = hi ? h : l;
                    unpack2(aN[b][p], l, h); aNv = hi ? h : l;
                    float r = sigm(aRv + x0c[b]*wxv[jj][0] + x1c[b]*wxv[jj][1] + bc0v[jj][0]);
                    float z = sigm(aZv + x0c[b]*wxv[jj][2] + x1c[b]*wxv[jj][3] + bc0v[jj][1]);
                    float n = tanh_(x0c[b]*wxv[jj][4] + x1c[b]*wxv[jj][5] + bc0v[jj][2]
                                    + r * (aNv + bc0v[jj][3]));
                    float hold = hd[((j0+jj) * BT + b0 + b) * 2];
                    hn0v[jj][b] = n + z * (hold - n);
                }
            }
            #pragma unroll
            for (int jj = 0; jj < 4; ++jj)
                #pragma unroll
                for (int b = 0; b < 4; ++b) {
                    float v = hn0v[jj][b];
                    *(float2*)(hd + ((j0+jj) * BT + b0 + b) * 2) = make_float2(v, v);
                }
            BAR_ALL();                     // sync2: hd0(t) + scrB visible

            // ---- phase 3: layer1 input-side GEMM k 0..63 (reads hd0 new) ----
            u64 cR[4][2], cZ[4][2], cNx[4][2], cNh[4][2];
            acc_zero(cR); acc_zero(cZ); acc_zero(cNx);
            gemm3<0, 64>(w1T, hd, j0, b0, cR, cZ, cNx);
            scr_reduce_l1(scrB, ht, cR, cZ, cNh);
            float hn1v[4][4];
            #pragma unroll
            for (int jj = 0; jj < 4; ++jj) {
                const int p = jj >> 1, hi = jj & 1;
                #pragma unroll
                for (int b = 0; b < 4; ++b) {
                    float l, h, cRv, cZv, cNxv, cNhv;
                    unpack2(cR[b][p],  l, h); cRv  = hi ? h : l;
                    unpack2(cZ[b][p],  l, h); cZv  = hi ? h : l;
                    unpack2(cNx[b][p], l, h); cNxv = hi ? h : l;
                    unpack2(cNh[b][p], l, h); cNhv = hi ? h : l;
                    float r = sigm(cRv + bc1v[jj][0]);
                    float z = sigm(cZv + bc1v[jj][1]);
                    float n = tanh_(cNxv + bc1v[jj][2] + r * (cNhv + bc1v[jj][3]));
                    float hold = hd[((64 + j0 + jj) * BT + b0 + b) * 2];
                    hn1v[jj][b] = n + z * (hold - n);
                }
            }
            #pragma unroll
            for (int jj = 0; jj < 4; ++jj)
                #pragma unroll
                for (int b = 0; b < 4; ++b) {
                    float v = hn1v[jj][b];
                    *(float2*)(hd + ((64 + j0 + jj) * BT + b0 + b) * 2) = make_float2(v, v);
                }
            BAR_ALL();                     // sync3: hd1(t) + scrA(t+1) visible

            #pragma unroll
            for (int b = 0; b < 4; ++b) { x0c[b] = nx0[b]; x1c[b] = nx1[b]; }
        } else {
            // ---- phase 2 (overlaps half-0 phase1+2): layer1 recurrent GEMM ----
            // k 64..127 reads hd1 = h1(t-1); writes partials to scrB.
            u64 cR[4][2], cZ[4][2], cNh[4][2];
            acc_zero(cR); acc_zero(cZ); acc_zero(cNh);
            gemm3<64, 128>(w1T, hd, j0, b0, cR, cZ, cNh);
            scr_write(scrB, ht, cR, cZ, cNh);
            BAR_ALL();                     // sync2

            // ---- phase 3 (overlaps half-0 phase3): next-step layer0 GEMM ----
            // k 32..63 reads hd0 = h0(t); writes partials to scrA for step t+1.
            u64 aR[4][2], aZ[4][2], aN[4][2];
            acc_zero(aR); acc_zero(aZ); acc_zero(aN);
            gemm3<32, 64>(w0T, hd, j0, b0, aR, aZ, aN);
            scr_write(scrA, ht, aR, aZ, aN);
            BAR_ALL();                     // sync3
        }
    }

    // ---- projection: out[b] = [h0f, h1f] @ Wp^T + bp ----
    if (tid < 128) {
        const int b = tid >> 2;      // 0..31
        const int seg = tid & 3;     // 0..3 -> 32 features each
        float s = 0.0f;
        #pragma unroll
        for (int c = seg * 32; c < seg * 32 + 32; ++c)
            s += Wp[c] * hd[(c * BT + b) * 2];
        s += __shfl_xor_sync(0xffffffffu, s, 1);
        s += __shfl_xor_sync(0xffffffffu, s, 2);
        if (seg == 0) out[blockIdx.x * BT + b] = s + bp[0];
    }
}

extern "C" void kernel_launch(void* const* d_in, const int* in_sizes, int n_in,
                              void* d_out, int out_size)
{
    (void)in_sizes; (void)n_in; (void)out_size;
    const float* x    = (const float*)d_in[0];
    const float* Wih0 = (const float*)d_in[1];
    const float* Whh0 = (const float*)d_in[2];
    const float* bih0 = (const float*)d_in[3];
    const float* bhh0 = (const float*)d_in[4];
    const float* Wih1 = (const float*)d_in[5];
    const float* Whh1 = (const float*)d_in[6];
    const float* bih1 = (const float*)d_in[7];
    const float* bhh1 = (const float*)d_in[8];
    const float* Wp   = (const float*)d_in[9];
    const float* bp   = (const float*)d_in[10];
    float* out = (float*)d_out;

    cudaFuncSetAttribute(gru2_kernel, cudaFuncAttributeMaxDynamicSharedMemorySize, SMEM_BYTES);
    gru2_kernel<<<NBLK, NTHR, SMEM_BYTES>>>(x, Wih0, Whh0, bih0, bhh0,
                                            Wih1, Whh1, bih1, bhh1, Wp, bp, out);
}